// round 14
// baseline (speedup 1.0000x reference)
#include <cuda_runtime.h>
#include <cstdint>

// ROI max pool via 2D sparse tables (log-max), round 14.
//   ro = r >> 1; amin = max(a-ro,0); amax = a+ro; if (amax > LIM) amax = LIM-1;
//   bin i: [amin + (i*len)/8, amin + ((i+1)*len+7)/8)  -- width always in [1,6]
// fm: (C=256, H=64, W=64) f32. out: (N, C, 8, 8) f32.
//
// Tables: TB[ky*3+kx][y][x][c] = max over fm[c][y..y+2^ky)[x..x+2^kx) (edge-
// clamped; clamped entries never consumed). Channel-innermost layout.
// Build reordered for parallelism:
//   Pass A (pool_y_fm): y-pooling FIRST, in fm layout (coalesced float4 over x):
//     YT[0]=max(rows y,y+1), YT[1]=max(rows y..y+3)  (rows clamped at 63).
//   Pass B (xpose_x): transpose + x-levels for 3 y-tiers (fm, YT0, YT1) ->
//     grid (8,64,3)=1536 CTAs (~10/SM; fixes build_x's 3.5-CTA/SM starvation).
//     tier t writes levels t*3 + kx.
// Main (= R8, ~17.2us, 80 regs, frozen): warp=(cb,ph-half); lane=pwsub*8+cquad
//   loads float4 (4 channels) per corner; 4 corners -> in-lane max; smem-staged
//   coalesced output.

namespace {
constexpr int Cdim  = 256;
constexpr int Hdim  = 64;
constexpr int Wdim  = 64;
constexpr int PLANE = Hdim * Wdim;              // 4096
constexpr int LVL   = PLANE * Cdim;             // floats per table level
constexpr int LVLB  = LVL * 4;                  // 4 MB per level
constexpr int YSTRB = Wdim * Cdim * 4;          // 65536
constexpr int XSTRB = Cdim * 4;                 // 1024
}

__device__ float TB[9 * LVL];                   // 36 MB tables (channel-innermost)
__device__ float YT[2 * LVL];                   // 8 MB y-pooled tiers (fm layout)

// ---------------- pass A: y-pooling in fm layout ----------------
// 262144 threads; thread = (c, y, x4): float4 over x. 4 loads, 2 stores.
__global__ __launch_bounds__(256)
void pool_y_fm(const float* __restrict__ fm)
{
    const int t  = blockIdx.x * 256 + threadIdx.x;  // 0..262143
    const int x4 = t & 15;
    const int y  = (t >> 4) & 63;
    const int c  = t >> 10;
    const int y1 = y + 1 > 63 ? 63 : y + 1;
    const int y2 = y + 2 > 63 ? 63 : y + 2;
    const int y3 = y + 3 > 63 ? 63 : y + 3;

    const float4* f4 = (const float4*)fm + (size_t)c * (PLANE / 4);
    const float4 a = f4[(y  << 4) + x4];
    const float4 b = f4[(y1 << 4) + x4];
    const float4 cc = f4[(y2 << 4) + x4];
    const float4 d = f4[(y3 << 4) + x4];

    float4 t1, t2;
    t1.x = fmaxf(a.x, b.x); t1.y = fmaxf(a.y, b.y);
    t1.z = fmaxf(a.z, b.z); t1.w = fmaxf(a.w, b.w);
    t2.x = fmaxf(t1.x, fmaxf(cc.x, d.x)); t2.y = fmaxf(t1.y, fmaxf(cc.y, d.y));
    t2.z = fmaxf(t1.z, fmaxf(cc.z, d.z)); t2.w = fmaxf(t1.w, fmaxf(cc.w, d.w));

    float4* yt = (float4*)YT;
    yt[t]                  = t1;   // tier ky=1
    yt[(LVL >> 2) + t]     = t2;   // tier ky=2
}

// ---------------- pass B: transpose + x-levels, 3 tiers ----------------
// grid (8 c-chunks, 64 y-rows, 3 tiers), block 256.
__global__ __launch_bounds__(256)
void xpose_x(const float* __restrict__ fm)
{
    const int c0   = blockIdx.x * 32;
    const int y0   = blockIdx.y;
    const int tier = blockIdx.z;                 // = ky

    const float* src = (tier == 0) ? fm : (YT + (size_t)(tier - 1) * LVL);

    __shared__ float S[64][33];

    for (int idx = threadIdx.x; idx < 64 * 32; idx += 256) {
        const int cc = idx >> 6;
        const int x  = idx & 63;
        S[x][cc] = src[(size_t)(c0 + cc) * PLANE + y0 * Wdim + x];
    }
    __syncthreads();

    const int lane = threadIdx.x & 31;
    const int warp = threadIdx.x >> 5;

    #pragma unroll
    for (int xi = 0; xi < 8; xi++) {
        const int x  = warp * 8 + xi;
        const int x1 = x + 1 > 63 ? 63 : x + 1;
        const int x2 = x + 2 > 63 ? 63 : x + 2;
        const int x3 = x + 3 > 63 ? 63 : x + 3;

        const float v0 = S[x][lane], v1 = S[x1][lane],
                    v2 = S[x2][lane], v3 = S[x3][lane];
        const float X1 = fmaxf(v0, v1);
        const float X2 = fmaxf(X1, fmaxf(v2, v3));

        float* o = TB + (size_t)(tier * 3) * LVL
                      + ((size_t)y0 * Wdim + x) * Cdim + c0 + lane;
        o[0]               = v0;   // (tier, kx0)
        o[LVL]             = X1;   // (tier, kx1)
        o[2 * (size_t)LVL] = X2;   // (tier, kx2)
    }
}

// ---------------- main kernel (R8 config, frozen) ----------------
// grid (4, N), block 128. bx: cb-group = bx>>1, ph-half = bx&1.
__global__ __launch_bounds__(128)
void roi_pool_main(const int4* __restrict__ rois, float* __restrict__ out)
{
    const int n    = blockIdx.y;
    const int warp = threadIdx.x >> 5;
    const int lane = threadIdx.x & 31;
    const int cb   = (blockIdx.x >> 1) * 4 + warp;   // 0..7
    const int phh  = blockIdx.x & 1;                 // ph half

    const int4 r = rois[n];
    const int yc = r.x, xc = r.y, rh = r.z, rw = r.w;
    const int roy = rh >> 1, rox = rw >> 1;

    int ymin = yc - roy; if (ymin < 0) ymin = 0;
    int ymax = yc + roy; if (ymax > Hdim) ymax = Hdim - 1;
    int xmin = xc - rox; if (xmin < 0) xmin = 0;
    int xmax = xc + rox; if (xmax > Wdim) xmax = Wdim - 1;

    const int leny = ymax - ymin;
    const int lenx = xmax - xmin;

    const int pwsub = lane >> 3;                 // 0..3
    const int cquad = lane & 7;                  // 0..7
    const int chb   = (cb * 32 + cquad * 4) * 4; // byte offset of lane's channels

    // x corner byte-offsets (incl. kx level term) for the two pw steps
    int xb0[2], xb1[2];
    #pragma unroll
    for (int s = 0; s < 2; s++) {
        const int pw = s * 4 + pwsub;
        const int cs = (pw * lenx) >> 3;
        const int ce = ((pw + 1) * lenx + 7) >> 3;
        const int rx = ce - cs;                            // 1..6
        const int kx = (rx >= 4) ? 2 : (rx >= 2 ? 1 : 0);  // 2^kx <= rx <= 2*2^kx
        xb0[s] = kx * LVLB + (xmin + cs) * XSTRB + chb;
        xb1[s] = kx * LVLB + (xmin + ce - (1 << kx)) * XSTRB + chb;
    }

    __shared__ float stage[4][16 * 36];
    float* st = stage[warp];

    const char* Bp = (const char*)TB;
    float* o = out + (size_t)n * (Cdim * 64) + cb * 32 * 64;

    #pragma unroll
    for (int php = 0; php < 2; php++) {          // two 16-bin chunks per warp
        #pragma unroll
        for (int ph2 = 0; ph2 < 2; ph2++) {
            const int ph = phh * 4 + php * 2 + ph2;
            const int rs = (ph * leny) >> 3;
            const int re = ((ph + 1) * leny + 7) >> 3;
            const int ry = re - rs;                            // 1..6
            const int ky = (ry >= 4) ? 2 : (ry >= 2 ? 1 : 0);
            const int ya0 = ky * 3 * LVLB + (ymin + rs) * YSTRB;
            const int ya1 = ky * 3 * LVLB + (ymin + re - (1 << ky)) * YSTRB;

            #pragma unroll
            for (int s = 0; s < 2; s++) {
                const float4 v00 = __ldg((const float4*)(Bp + ya0 + xb0[s]));
                const float4 v01 = __ldg((const float4*)(Bp + ya0 + xb1[s]));
                const float4 v10 = __ldg((const float4*)(Bp + ya1 + xb0[s]));
                const float4 v11 = __ldg((const float4*)(Bp + ya1 + xb1[s]));
                float4 m;
                m.x = fmaxf(fmaxf(v00.x, v01.x), fmaxf(v10.x, v11.x));
                m.y = fmaxf(fmaxf(v00.y, v01.y), fmaxf(v10.y, v11.y));
                m.z = fmaxf(fmaxf(v00.z, v01.z), fmaxf(v10.z, v11.z));
                m.w = fmaxf(fmaxf(v00.w, v01.w), fmaxf(v10.w, v11.w));

                const int bl = ph2 * 8 + s * 4 + pwsub;        // 0..15
                *(float4*)(st + bl * 36 + cquad * 4) = m;
            }
        }
        __syncwarp();

        // coalesced chunk writeback: 16 bins x 32 channels
        const int base = (phh * 2 + php) * 16;   // global bin offset of chunk
        #pragma unroll
        for (int i = 0; i < 16; i++) {
            const int g   = i * 32 + lane;
            const int cc  = g >> 4;              // channel within block (0..31)
            const int b16 = g & 15;              // bin within chunk
            o[cc * 64 + base + b16] = st[b16 * 36 + cc];
        }
        __syncwarp();                            // WAR before next chunk's stores
    }
}

extern "C" void kernel_launch(void* const* d_in, const int* in_sizes, int n_in,
                              void* d_out, int out_size)
{
    const float* fm   = (const float*)d_in[0];
    const int4*  rois = (const int4*)d_in[1];
    float*       out  = (float*)d_out;
    const int N = in_sizes[1] / 4;

    pool_y_fm<<<1024, 256>>>(fm);
    xpose_x<<<dim3(8, 64, 3), 256>>>(fm);
    roi_pool_main<<<dim3(4, N), 128>>>(rois, out);
}

// round 15
// speedup vs baseline: 1.4822x; 1.4822x over previous
#include <cuda_runtime.h>
#include <cuda_fp16.h>
#include <cstdint>

// ROI max pool via 2D sparse tables (log-max), round 15: fp16 tables.
//   ro = r >> 1; amin = max(a-ro,0); amax = a+ro; if (amax > LIM) amax = LIM-1;
//   bin i: [amin + (i*len)/8, amin + ((i+1)*len+7)/8)  -- width always in [1,6]
// fm: (C=256, H=64, W=64) f32. out: (N, C, 8, 8) f32.
//
// fp16 is exact for max-composition: round-to-nearest is monotone, so
// half(max(a,b)) == max(half(a),half(b)); total error = input quantization
// only, bounded by 2^-11 relative (< 1e-3 threshold).
//
// TBh[tier*3+kx][y][x][c] (half, channel-innermost) = max over
// fm[c][y..y+2^tier)[x..x+2^kx), edge-clamped (clamped entries never consumed).
// build_half: ONE kernel, grid (8 c-chunks, 64 y, 3 tiers); loads its own
//   (1/2/4) halo rows straight from fm (L2-resident), transposes via smem,
//   computes x-levels, stores half.
// roi_pool_main: warp = one 32-channel block, ALL 64 bins. lane = pw*4+cq;
//   each corner load is LDG.128 = 8 fp16 channels; 4 corners -> __hmax2 tree;
//   32 LDG.128 per warp total. f32 staging (36-pad) + coalesced writeback.

namespace {
constexpr int Cdim  = 256;
constexpr int Hdim  = 64;
constexpr int Wdim  = 64;
constexpr int PLANE = Hdim * Wdim;               // 4096
constexpr int LVL   = PLANE * Cdim;              // elements per table level
constexpr int LVLB2 = LVL * 2;                   // bytes per level (half) = 2 MB
constexpr int YSTRB = Wdim * Cdim * 2;           // 32768
constexpr int XSTRB = Cdim * 2;                  // 512
}

__device__ __half TBh[9 * LVL];                  // 18 MB fp16 tables

// ---------------- build: transpose + x-levels, 3 y-tiers, one kernel --------
template<int R>
__device__ __forceinline__
void load_rows(float (*S)[33], const float* __restrict__ fm, int c0, int y0, int tid)
{
    for (int idx = tid; idx < 64 * 32; idx += 256) {
        const int cc = idx >> 6;
        const int x  = idx & 63;
        const float* base = fm + (size_t)(c0 + cc) * PLANE + x;
        float m = base[y0 * Wdim];
        #pragma unroll
        for (int r = 1; r < R; r++) {
            int gy = y0 + r; if (gy > 63) gy = 63;
            m = fmaxf(m, base[gy * Wdim]);
        }
        S[x][cc] = m;
    }
}

__global__ __launch_bounds__(256)
void build_half(const float* __restrict__ fm)
{
    const int c0   = blockIdx.x * 32;
    const int y0   = blockIdx.y;
    const int tier = blockIdx.z;                 // = ky

    __shared__ float S[64][33];

    if (tier == 0)      load_rows<1>(S, fm, c0, y0, threadIdx.x);
    else if (tier == 1) load_rows<2>(S, fm, c0, y0, threadIdx.x);
    else                load_rows<4>(S, fm, c0, y0, threadIdx.x);
    __syncthreads();

    const int lane = threadIdx.x & 31;
    const int warp = threadIdx.x >> 5;

    #pragma unroll
    for (int xi = 0; xi < 8; xi++) {
        const int x  = warp * 8 + xi;
        const int x1 = x + 1 > 63 ? 63 : x + 1;
        const int x2 = x + 2 > 63 ? 63 : x + 2;
        const int x3 = x + 3 > 63 ? 63 : x + 3;

        const float v0 = S[x][lane], v1 = S[x1][lane],
                    v2 = S[x2][lane], v3 = S[x3][lane];
        const float X1 = fmaxf(v0, v1);
        const float X2 = fmaxf(X1, fmaxf(v2, v3));

        __half* o = TBh + (size_t)(tier * 3) * LVL
                        + ((size_t)y0 * Wdim + x) * Cdim + c0 + lane;
        o[0]               = __float2half(v0);   // (tier, kx0)
        o[LVL]             = __float2half(X1);   // (tier, kx1)
        o[2 * (size_t)LVL] = __float2half(X2);   // (tier, kx2)
    }
}

// ---------------- main kernel ----------------
// grid (2, N), block 128. Warp -> channel block cb = bx*4 + warp (0..7).
// lane = pw*4 + cq: bin column pw (0..7), channel octet cq (0..3; 8 ch each).
__global__ __launch_bounds__(128)
void roi_pool_main(const int4* __restrict__ rois, float* __restrict__ out)
{
    const int n    = blockIdx.y;
    const int warp = threadIdx.x >> 5;
    const int lane = threadIdx.x & 31;
    const int cb   = blockIdx.x * 4 + warp;      // 0..7

    const int4 r = rois[n];
    const int yc = r.x, xc = r.y, rh = r.z, rw = r.w;
    const int roy = rh >> 1, rox = rw >> 1;

    int ymin = yc - roy; if (ymin < 0) ymin = 0;
    int ymax = yc + roy; if (ymax > Hdim) ymax = Hdim - 1;
    int xmin = xc - rox; if (xmin < 0) xmin = 0;
    int xmax = xc + rox; if (xmax > Wdim) xmax = Wdim - 1;

    const int leny = ymax - ymin;
    const int lenx = xmax - xmin;

    const int pw = lane >> 2;                    // 0..7
    const int cq = lane & 3;                     // 0..3
    const int chb = cb * 64 + cq * 16;           // byte offset of lane's 8 channels

    // this lane's x-corner byte offsets (incl. kx level select)
    const int cs = (pw * lenx) >> 3;
    const int ce = ((pw + 1) * lenx + 7) >> 3;
    const int rx = ce - cs;                                // 1..6
    const int kx = (rx >= 4) ? 2 : (rx >= 2 ? 1 : 0);      // 2^kx <= rx <= 2*2^kx
    const int xb0 = kx * LVLB2 + (xmin + cs) * XSTRB + chb;
    const int xb1 = kx * LVLB2 + (xmin + ce - (1 << kx)) * XSTRB + chb;

    __shared__ float stage[4][32 * 36];
    float* st = stage[warp];

    const char* Bp = (const char*)TBh;
    float* o = out + (size_t)n * (Cdim * 64) + cb * 32 * 64;

    #pragma unroll
    for (int half_ = 0; half_ < 2; half_++) {    // two 32-bin chunks (4 ph each)
        #pragma unroll
        for (int p2 = 0; p2 < 4; p2++) {
            const int ph = half_ * 4 + p2;
            const int rs = (ph * leny) >> 3;
            const int re = ((ph + 1) * leny + 7) >> 3;
            const int ry = re - rs;                          // 1..6
            const int ky = (ry >= 4) ? 2 : (ry >= 2 ? 1 : 0);
            const int ya0 = ky * 3 * LVLB2 + (ymin + rs) * YSTRB;
            const int ya1 = ky * 3 * LVLB2 + (ymin + re - (1 << ky)) * YSTRB;

            uint4 u00 = __ldg((const uint4*)(Bp + ya0 + xb0));
            uint4 u01 = __ldg((const uint4*)(Bp + ya0 + xb1));
            uint4 u10 = __ldg((const uint4*)(Bp + ya1 + xb0));
            uint4 u11 = __ldg((const uint4*)(Bp + ya1 + xb1));

            const __half2* a = (const __half2*)&u00;
            const __half2* b = (const __half2*)&u01;
            const __half2* c = (const __half2*)&u10;
            const __half2* d = (const __half2*)&u11;

            __half2 m0 = __hmax2(__hmax2(a[0], b[0]), __hmax2(c[0], d[0]));
            __half2 m1 = __hmax2(__hmax2(a[1], b[1]), __hmax2(c[1], d[1]));
            __half2 m2 = __hmax2(__hmax2(a[2], b[2]), __hmax2(c[2], d[2]));
            __half2 m3 = __hmax2(__hmax2(a[3], b[3]), __hmax2(c[3], d[3]));

            const float2 f0 = __half22float2(m0);
            const float2 f1 = __half22float2(m1);
            const float2 f2 = __half22float2(m2);
            const float2 f3 = __half22float2(m3);

            const int bl = p2 * 8 + pw;          // bin within 32-bin chunk
            float* sp = st + bl * 36 + cq * 8;
            *(float4*)(sp)     = make_float4(f0.x, f0.y, f1.x, f1.y);
            *(float4*)(sp + 4) = make_float4(f2.x, f2.y, f3.x, f3.y);
        }
        __syncwarp();

        // coalesced writeback: 32 bins x 32 channels for this chunk
        const int base = half_ * 32;
        #pragma unroll
        for (int i = 0; i < 32; i++) {
            // iteration i: channel c = i, bin = lane
            o[i * 64 + base + lane] = st[lane * 36 + i];
        }
        __syncwarp();                            // WAR before next chunk's stores
    }
}

extern "C" void kernel_launch(void* const* d_in, const int* in_sizes, int n_in,
                              void* d_out, int out_size)
{
    const float* fm   = (const float*)d_in[0];
    const int4*  rois = (const int4*)d_in[1];
    float*       out  = (float*)d_out;
    const int N = in_sizes[1] / 4;

    build_half<<<dim3(8, 64, 3), 256>>>(fm);
    roi_pool_main<<<dim3(2, N), 128>>>(rois, out);
}